// round 16
// baseline (speedup 1.0000x reference)
#include <cuda_runtime.h>
#include <cuda_bf16.h>
#include <math.h>

#define Bb   64
#define NJv  30
#define NMv  20
#define Nn   600
#define Hd   128
#define NT   (Bb*Nn)
#define MAXNB 64
#define LD   132
#define INV_NT (1.f/38400.f)

// output layout (float32, reference tuple order, flattened+concatenated)
#define O_ENT 0
#define O_V   64
#define O_LOGA 128
#define O_AN  192
#define O_AF  (192+1280)
#define O_MMA (O_AF+8192)
#define O_HP  (O_MMA+1280)

// ---------------- device scratch (no allocations) ----------------
__device__ float d_t[(size_t)NT*Hd];
__device__ float d_g[(size_t)NT*Hd];
__device__ float d_p[(size_t)NT*Hd];
__device__ unsigned short d_nbr[(size_t)NT*MAXNB];
__device__ int   d_cnt[NT];
__device__ float d_ssum[4*Hd];
__device__ float d_ssq[4*Hd];
__device__ float d_hp[Bb*Hd];
__device__ int   d_boolcode;

// ---------------- helpers ----------------
__device__ __forceinline__ unsigned long long pk2(float a, float b){
    unsigned long long r;
    asm("mov.b64 %0, {%1,%2};" : "=l"(r) : "f"(a), "f"(b));
    return r;
}
__device__ __forceinline__ void upk(unsigned long long v, float& lo, float& hi){
    asm("mov.b64 {%0,%1}, %2;" : "=f"(lo), "=f"(hi) : "l"(v));
}
__device__ __forceinline__ void ffma2(unsigned long long& d, unsigned long long a, unsigned long long b){
    asm("fma.rn.f32x2 %0, %1, %2, %0;" : "+l"(d) : "l"(a), "l"(b));
}
__device__ __forceinline__ bool rdb(const void* p, long long i, int code){
    if (code == 0) return ((const unsigned char*)p)[i] != 0;
    if (code == 1) return ((const int*)p)[i] != 0;
    return ((const float*)p)[i] != 0.f;
}
__device__ __forceinline__ float wredsum(float v){
    #pragma unroll
    for (int o = 16; o; o >>= 1) v += __shfl_xor_sync(0xffffffffu, v, o);
    return v;
}
__device__ __forceinline__ void bn_of(int slot, int k, float& mean, float& istd){
    float m = d_ssum[slot*Hd + k] * INV_NT;
    float v = d_ssq[slot*Hd + k] * INV_NT - m*m;
    if (v < 0.f) v = 0.f;
    mean = m;
    istd = rsqrtf(v + 1e-5f);
}
#define NEGINF __int_as_float(0xff800000)

// ---------------- init: zero stats + bool dtype sniff ----------------
__global__ void k_init(const unsigned char* m){
    __shared__ int f0, fx;
    int tid = threadIdx.x;
    if (tid == 0){ f0 = 0; fx = 0; }
    for (int i = tid; i < 4*Hd; i += 256){ d_ssum[i] = 0.f; d_ssq[i] = 0.f; }
    __syncthreads();
    for (int i = tid; i < Bb*NJv; i += 256){
        if (m[i]){ if ((i & 3) == 0) atomicOr(&f0, 1); else atomicOr(&fx, 1); }
    }
    __syncthreads();
    if (tid == 0){
        int code;
        if (f0 && fx) code = 0;        // bytes everywhere -> uint8 bool
        else if (f0)  code = 1;        // only byte0 of each word -> int32
        else if (fx)  code = 2;        // only high bytes -> float32
        else          code = 0;
        d_boolcode = code;
    }
}

// ---------------- adj scan + pooled0 + t1 + stats slot0 ----------------
__global__ void __launch_bounds__(256) k_build(const float* __restrict__ adj,
                                               const float* __restrict__ x,
                                               const float* __restrict__ W1,
                                               const float* __restrict__ b1){
    __shared__ float s_sum[Hd], s_sq[Hd];
    for (int i = threadIdx.x; i < Hd; i += 256){ s_sum[i] = 0.f; s_sq[i] = 0.f; }
    __syncthreads();
    int warp = (blockIdx.x*256 + threadIdx.x) >> 5;
    int lane = threadIdx.x & 31;
    int b = warp / Nn;
    const float* arow = adj + (size_t)warp*Nn;
    float s0 = 0.f, s1 = 0.f;
    int cnt = 0;
    for (int base = 0; base < Nn; base += 32){
        int m = base + lane;
        float v = (m < Nn) ? arow[m] : 0.f;
        unsigned bm = __ballot_sync(0xffffffffu, v != 0.f);
        if (v != 0.f){
            int pos = cnt + __popc(bm & ((1u << lane) - 1u));
            if (pos < MAXNB) d_nbr[(size_t)warp*MAXNB + pos] = (unsigned short)m;
            float2 xv = ((const float2*)x)[b*Nn + m];
            s0 += xv.x; s1 += xv.y;
        }
        cnt += __popc(bm);
    }
    if (lane == 0) d_cnt[warp] = cnt > MAXNB ? MAXNB : cnt;
    #pragma unroll
    for (int o = 16; o; o >>= 1){
        s0 += __shfl_xor_sync(0xffffffffu, s0, o);
        s1 += __shfl_xor_sync(0xffffffffu, s1, o);
    }
    float* trow = d_t + (size_t)warp*Hd;
    #pragma unroll
    for (int i = 0; i < 4; i++){
        int d = lane + 32*i;
        float tv = fmaf(s0, W1[d], fmaf(s1, W1[Hd + d], b1[d]));
        trow[d] = tv;
        atomicAdd(&s_sum[d], tv);
        atomicAdd(&s_sq[d], tv*tv);
    }
    __syncthreads();
    for (int i = threadIdx.x; i < Hd; i += 256){
        atomicAdd(&d_ssum[i], s_sum[i]);
        atomicAdd(&d_ssq[i],  s_sq[i]);
    }
}

// ---------------- big GEMM: OUT = act(A) @ W + bias, stats(slotOut) ----------------
// Asel: 0->d_t 1->d_p ; Osel: 0->d_g 1->d_t ; mode 1 -> bn(slotIn)+relu on A-load
__global__ void __launch_bounds__(256, 2) k_gemm(const float* __restrict__ W,
                                                 const float* __restrict__ bias,
                                                 int Asel, int Osel, int mode,
                                                 int slotIn, int slotOut){
    extern __shared__ float sm[];
    float* Ws     = sm;                 // [128][LD]  (k-major)
    float* As     = sm + Hd*LD;         // [32][LD]   (k-chunk, transposed: [k][row])
    float* s_sum  = As + 32*LD;         // [128]
    float* s_sq   = s_sum + Hd;         // [128]
    float* s_mean = s_sq + Hd;          // [128]
    float* s_istd = s_mean + Hd;        // [128]
    const float* A   = Asel ? d_p : d_t;
    float*       OUT = Osel ? d_t : d_g;
    const int tid = threadIdx.x;
    const int rowBase = blockIdx.x * 128;

    for (int i = tid; i < Hd; i += 256){
        s_sum[i] = 0.f; s_sq[i] = 0.f;
        if (mode){
            float m, is; bn_of(slotIn, i, m, is);
            s_mean[i] = m; s_istd[i] = is;
        }
    }
    // stage W [k][c]
    for (int i = tid; i < Hd*32; i += 256){
        int k = i >> 5, c4 = i & 31;
        float4 w = ((const float4*)W)[k*32 + c4];
        *(float4*)(Ws + k*LD + c4*4) = w;
    }

    const int tx = tid & 15, ty = tid >> 4;
    const int r0 = ty*8;
    unsigned long long acc[4][8];
    #pragma unroll
    for (int p = 0; p < 4; p++)
        #pragma unroll
        for (int c = 0; c < 8; c++) acc[p][c] = 0ull;

    const int srow = tid >> 1;
    const int kh   = (tid & 1) * 16;

    for (int kc = 0; kc < 4; kc++){
        __syncthreads();
        // stage A chunk transposed with fused activation
        {
            const float* ar = A + (size_t)(rowBase + srow)*Hd + kc*32 + kh;
            #pragma unroll
            for (int j4 = 0; j4 < 4; j4++){
                float4 a = ((const float4*)ar)[j4];
                int kk = kh + j4*4;
                if (mode){
                    int kg = kc*32 + kk;
                    a.x = fmaxf((a.x - s_mean[kg+0])*s_istd[kg+0], 0.f);
                    a.y = fmaxf((a.y - s_mean[kg+1])*s_istd[kg+1], 0.f);
                    a.z = fmaxf((a.z - s_mean[kg+2])*s_istd[kg+2], 0.f);
                    a.w = fmaxf((a.w - s_mean[kg+3])*s_istd[kg+3], 0.f);
                }
                As[(kk+0)*LD + srow] = a.x;
                As[(kk+1)*LD + srow] = a.y;
                As[(kk+2)*LD + srow] = a.z;
                As[(kk+3)*LD + srow] = a.w;
            }
        }
        __syncthreads();
        #pragma unroll 2
        for (int kk = 0; kk < 32; kk++){
            const float* ak = As + kk*LD + r0;
            unsigned long long a0 = *(const unsigned long long*)(ak + 0);
            unsigned long long a1 = *(const unsigned long long*)(ak + 2);
            unsigned long long a2 = *(const unsigned long long*)(ak + 4);
            unsigned long long a3 = *(const unsigned long long*)(ak + 6);
            const float* wk = Ws + (kc*32 + kk)*LD + tx;
            #pragma unroll
            for (int c = 0; c < 8; c++){
                float wv = wk[16*c];
                unsigned long long wd = pk2(wv, wv);
                ffma2(acc[0][c], a0, wd);
                ffma2(acc[1][c], a1, wd);
                ffma2(acc[2][c], a2, wd);
                ffma2(acc[3][c], a3, wd);
            }
        }
    }
    // epilogue: bias, store, BN stats
    #pragma unroll
    for (int c = 0; c < 8; c++){
        int col = tx + 16*c;
        float bv = bias[col];
        float psum = 0.f, psq = 0.f;
        #pragma unroll
        for (int p = 0; p < 4; p++){
            float lo, hi; upk(acc[p][c], lo, hi);
            lo += bv; hi += bv;
            OUT[(size_t)(rowBase + r0 + 2*p)*Hd + col] = lo;
            OUT[(size_t)(rowBase + r0 + 2*p + 1)*Hd + col] = hi;
            psum += lo + hi;
            psq  += lo*lo + hi*hi;
        }
        atomicAdd(&s_sum[col], psum);
        atomicAdd(&s_sq[col],  psq);
    }
    __syncthreads();
    for (int i = tid; i < Hd; i += 256){
        atomicAdd(&d_ssum[slotOut*Hd + i], s_sum[i]);
        atomicAdd(&d_ssq[slotOut*Hd + i],  s_sq[i]);
    }
}

// ---------------- SpMM: pooled1 = sum over neighbors of relu(bn1(g)) ----------------
__global__ void __launch_bounds__(256) k_spmm(){
    int warp = (blockIdx.x*256 + threadIdx.x) >> 5;
    int lane = threadIdx.x & 31;
    int cnt = d_cnt[warp];
    int b = warp / Nn;
    const unsigned short* nb = d_nbr + (size_t)warp*MAXNB;
    float4 m4, i4;
    bn_of(1, lane*4 + 0, m4.x, i4.x);
    bn_of(1, lane*4 + 1, m4.y, i4.y);
    bn_of(1, lane*4 + 2, m4.z, i4.z);
    bn_of(1, lane*4 + 3, m4.w, i4.w);
    float s0 = 0.f, s1 = 0.f, s2 = 0.f, s3 = 0.f;
    for (int j = 0; j < cnt; j++){
        int node = nb[j];
        float4 g = ((const float4*)(d_g + (size_t)(b*Nn + node)*Hd))[lane];
        s0 += fmaxf((g.x - m4.x)*i4.x, 0.f);
        s1 += fmaxf((g.y - m4.y)*i4.y, 0.f);
        s2 += fmaxf((g.z - m4.z)*i4.z, 0.f);
        s3 += fmaxf((g.w - m4.w)*i4.w, 0.f);
    }
    ((float4*)(d_p + (size_t)warp*Hd))[lane] = make_float4(s0, s1, s2, s3);
}

// ---------------- graph pooling: h_pooled[b] = sum_n gp[b,n]*relu(bn3(g[b,n])) ----------------
__global__ void __launch_bounds__(512) k_hpool(const float* __restrict__ gp, float* __restrict__ out){
    __shared__ float part[4][Hd];
    int b = blockIdx.x;
    int d = threadIdx.x & 127;
    int sl = threadIdx.x >> 7;
    float m, is; bn_of(3, d, m, is);
    float s = 0.f;
    int n0 = sl*150, n1 = n0 + 150;
    #pragma unroll 4
    for (int n = n0; n < n1; n++){
        float g = d_g[(size_t)(b*Nn + n)*Hd + d];
        s += gp[b*Nn + n] * fmaxf((g - m)*is, 0.f);
    }
    part[sl][d] = s;
    __syncthreads();
    if (sl == 0){
        float t = part[0][d] + part[1][d] + part[2][d] + part[3][d];
        d_hp[b*Hd + d] = t;
        out[O_HP + b*Hd + d] = t;
    }
}

// ---------------- fused head: actor MLP + softmax + critic + gathers ----------------
// 256 threads: two groups of 128; group g handles candidates [g*15, g*15+15)
__global__ void __launch_bounds__(256) k_head(
    const int* __restrict__ candidate, const void* __restrict__ mask,
    const void* __restrict__ mask_mch, const float* __restrict__ dur,
    const int* __restrict__ a_index, const int* __restrict__ old_action,
    const float* __restrict__ mch_pool,
    const float* __restrict__ Wa1, const float* __restrict__ ba1,
    const float* __restrict__ Wa2, const float* __restrict__ ba2,
    const float* __restrict__ Wa3, const float* __restrict__ ba3,
    const float* __restrict__ Wc1, const float* __restrict__ bc1,
    const float* __restrict__ Wc2, const float* __restrict__ bc2,
    float* __restrict__ out)
{
    __shared__ float Abuf[NJv][Hd];
    __shared__ float Bbuf[NJv][Hd];
    __shared__ float hp_s[Hd], mp_s[Hd];
    __shared__ float scores[32];
    __shared__ float red[4];
    int b = blockIdx.x;
    int tid = threadIdx.x;
    int d = tid & 127;
    int grp = tid >> 7;
    int lane = tid & 31, wid = tid >> 5;
    int code = d_boolcode;
    float mn3, is3; bn_of(3, d, mn3, is3);

    if (grp == 0){
        hp_s[d] = d_hp[b*Hd + d];
        mp_s[d] = mch_pool[b*Hd + d];
    }
    for (int j = grp; j < NJv; j += 2){
        int node = candidate[b*NJv + j];
        float g = d_g[(size_t)(b*Nn + node)*Hd + d];
        Abuf[j][d] = fmaxf((g - mn3)*is3, 0.f);
    }
    __syncthreads();

    // actor layer 1 — shared (h_pooled, mch_pool) contribution once per thread
    float bs = ba1[d];
    for (int k = 0; k < Hd; k++){
        bs = fmaf(hp_s[k], Wa1[(Hd + k)*Hd + d], bs);
        bs = fmaf(mp_s[k], Wa1[(2*Hd + k)*Hd + d], bs);
    }
    const int j0 = grp * 15;
    {
        float accj[15];
        #pragma unroll
        for (int j = 0; j < 15; j++) accj[j] = bs;
        for (int k = 0; k < Hd; k += 4){
            float w0 = Wa1[(k+0)*Hd + d];
            float w1 = Wa1[(k+1)*Hd + d];
            float w2 = Wa1[(k+2)*Hd + d];
            float w3 = Wa1[(k+3)*Hd + d];
            #pragma unroll
            for (int j = 0; j < 15; j++){
                float4 a = *(const float4*)&Abuf[j0 + j][k];
                accj[j] = fmaf(a.x, w0, accj[j]);
                accj[j] = fmaf(a.y, w1, accj[j]);
                accj[j] = fmaf(a.z, w2, accj[j]);
                accj[j] = fmaf(a.w, w3, accj[j]);
            }
        }
        #pragma unroll
        for (int j = 0; j < 15; j++) Bbuf[j0 + j][d] = tanhf(accj[j]);
    }
    __syncthreads();
    // actor layer 2
    {
        float accj[15];
        float b2 = ba2[d];
        #pragma unroll
        for (int j = 0; j < 15; j++) accj[j] = b2;
        for (int k = 0; k < Hd; k += 4){
            float w0 = Wa2[(k+0)*Hd + d];
            float w1 = Wa2[(k+1)*Hd + d];
            float w2 = Wa2[(k+2)*Hd + d];
            float w3 = Wa2[(k+3)*Hd + d];
            #pragma unroll
            for (int j = 0; j < 15; j++){
                float4 a = *(const float4*)&Bbuf[j0 + j][k];
                accj[j] = fmaf(a.x, w0, accj[j]);
                accj[j] = fmaf(a.y, w1, accj[j]);
                accj[j] = fmaf(a.z, w2, accj[j]);
                accj[j] = fmaf(a.w, w3, accj[j]);
            }
        }
        #pragma unroll
        for (int j = 0; j < 15; j++) Abuf[j0 + j][d] = tanhf(accj[j]);
    }
    __syncthreads();
    // scores: 8 warps, warp-parallel dot with Wa3
    {
        float4 wv = ((const float4*)Wa3)[lane];
        for (int j = wid; j < NJv; j += 8){
            float4 av = ((const float4*)Abuf[j])[lane];
            float p = av.x*wv.x + av.y*wv.y + av.z*wv.z + av.w*wv.w;
            p = wredsum(p);
            if (lane == 0) scores[j] = (p + ba3[0]) * 10.f;
        }
    }
    // critic (group 0: 4 warps)
    if (grp == 0){
        float c = bc1[d];
        for (int k = 0; k < Hd; k++) c = fmaf(hp_s[k], Wc1[k*Hd + d], c);
        c = tanhf(c);
        float pv = wredsum(c * Wc2[d]);
        if (lane == 0) red[wid] = pv;
    }
    __syncthreads();
    if (tid == 0) out[O_V + b] = red[0] + red[1] + red[2] + red[3] + bc2[0];
    // softmax / entropy / log_a on warp 0
    if (wid == 0){
        float s = (lane < NJv) ? scores[lane] : NEGINF;
        if (lane < NJv && rdb(mask, (long long)b*NJv + lane, code)) s = NEGINF;
        float mx = s;
        #pragma unroll
        for (int o = 16; o; o >>= 1) mx = fmaxf(mx, __shfl_xor_sync(0xffffffffu, mx, o));
        float e = (s == NEGINF) ? 0.f : expf(s - mx);
        float se = wredsum(e);
        float lse = mx + logf(se);
        float logpi = s - lse;
        float pi = e / se;
        float ent = (pi > 0.f) ? (-pi * logpi) : 0.f;
        ent = wredsum(ent);
        if (lane == 0) out[O_ENT + b] = ent;
        int ai = a_index[b];
        if (lane == ai) out[O_LOGA + b] = logpi;
    }
    // gathers
    {
        int oa = old_action[b];
        if (grp == 0){
            float g = d_g[(size_t)(b*Nn + oa)*Hd + d];
            out[O_AF + b*Hd + d] = fmaxf((g - mn3)*is3, 0.f);
        }
        if (tid < NMv){
            out[O_AN + b*NMv + tid] = dur[(size_t)(b*Nn + oa)*NMv + tid];
            out[O_MMA + b*NMv + tid] = rdb(mask_mch, (long long)(b*Nn + oa)*NMv + tid, code) ? 1.f : 0.f;
        }
    }
}

// ---------------- launcher ----------------
extern "C" void kernel_launch(void* const* d_in, const int* in_sizes, int n_in,
                              void* d_out, int out_size) {
    const float* x         = (const float*)d_in[0];
    const float* graphpool = (const float*)d_in[1];
    // d_in[2] padded_nei unused
    const float* adj       = (const float*)d_in[3];
    const int*   candidate = (const int*)d_in[4];
    const void*  mask      = d_in[5];
    const void*  mask_mch  = d_in[6];
    const float* dur       = (const float*)d_in[7];
    const int*   a_index   = (const int*)d_in[8];
    const int*   old_act   = (const int*)d_in[9];
    const float* mch_pool  = (const float*)d_in[10];
    const float* W1_0 = (const float*)d_in[11]; const float* b1_0 = (const float*)d_in[12];
    const float* W2_0 = (const float*)d_in[13]; const float* b2_0 = (const float*)d_in[14];
    const float* W1_1 = (const float*)d_in[15]; const float* b1_1 = (const float*)d_in[16];
    const float* W2_1 = (const float*)d_in[17]; const float* b2_1 = (const float*)d_in[18];
    const float* Wa1  = (const float*)d_in[19]; const float* ba1  = (const float*)d_in[20];
    const float* Wa2  = (const float*)d_in[21]; const float* ba2  = (const float*)d_in[22];
    const float* Wa3  = (const float*)d_in[23]; const float* ba3  = (const float*)d_in[24];
    const float* Wc1  = (const float*)d_in[25]; const float* bc1  = (const float*)d_in[26];
    const float* Wc2  = (const float*)d_in[27]; const float* bc2  = (const float*)d_in[28];
    float* out = (float*)d_out;

    const int GEMM_SMEM = (Hd*LD + 32*LD + 4*Hd) * (int)sizeof(float);  // 86528
    cudaFuncSetAttribute(k_gemm, cudaFuncAttributeMaxDynamicSharedMemorySize, GEMM_SMEM);

    k_init<<<1, 256>>>((const unsigned char*)mask);                // zero stats + bool sniff
    k_build<<<NT/8, 256>>>(adj, x, W1_0, b1_0);                    // t1 -> d_t, stats0
    k_gemm<<<NT/128, 256, GEMM_SMEM>>>(W2_0, b2_0, 0, 0, 1, 0, 1); // t2 -> d_g, stats1
    k_spmm<<<NT/8, 256>>>();                                       // pooled1 -> d_p
    k_gemm<<<NT/128, 256, GEMM_SMEM>>>(W1_1, b1_1, 1, 1, 0, 0, 2); // t3 -> d_t, stats2
    k_gemm<<<NT/128, 256, GEMM_SMEM>>>(W2_1, b2_1, 0, 0, 1, 2, 3); // t4 -> d_g, stats3  (6th launch -> ncu)
    k_hpool<<<Bb, 512>>>(graphpool, out);
    k_head<<<Bb, 256>>>(candidate, mask, mask_mch, dur, a_index, old_act, mch_pool,
                        Wa1, ba1, Wa2, ba2, Wa3, ba3, Wc1, bc1, Wc2, bc2, out);
}

// round 17
// speedup vs baseline: 1.1685x; 1.1685x over previous
#include <cuda_runtime.h>
#include <cuda_bf16.h>
#include <math.h>

#define Bb   64
#define NJv  30
#define NMv  20
#define Nn   600
#define Hd   128
#define NT   (Bb*Nn)
#define MAXNB 64
#define LDW  132
#define LDA  66
#define INV_NT (1.f/38400.f)

// output layout (float32, reference tuple order, flattened+concatenated)
#define O_ENT 0
#define O_V   64
#define O_LOGA 128
#define O_AN  192
#define O_AF  (192+1280)
#define O_MMA (O_AF+8192)
#define O_HP  (O_MMA+1280)

// ---------------- device scratch (no allocations) ----------------
__device__ float d_t[(size_t)NT*Hd];
__device__ float d_g[(size_t)NT*Hd];
__device__ float d_p[(size_t)NT*Hd];
__device__ unsigned short d_nbr[(size_t)NT*MAXNB];
__device__ int   d_cnt[NT];
__device__ float d_ssum[4*Hd];
__device__ float d_ssq[4*Hd];
__device__ float d_hp[Bb*Hd];
__device__ int   d_boolcode;

// ---------------- helpers ----------------
__device__ __forceinline__ unsigned long long pk2(float a, float b){
    unsigned long long r;
    asm("mov.b64 %0, {%1,%2};" : "=l"(r) : "f"(a), "f"(b));
    return r;
}
__device__ __forceinline__ void upk(unsigned long long v, float& lo, float& hi){
    asm("mov.b64 {%0,%1}, %2;" : "=f"(lo), "=f"(hi) : "l"(v));
}
__device__ __forceinline__ void ffma2(unsigned long long& d, unsigned long long a, unsigned long long b){
    asm("fma.rn.f32x2 %0, %1, %2, %0;" : "+l"(d) : "l"(a), "l"(b));
}
__device__ __forceinline__ bool rdb(const void* p, long long i, int code){
    if (code == 0) return ((const unsigned char*)p)[i] != 0;
    if (code == 1) return ((const int*)p)[i] != 0;
    return ((const float*)p)[i] != 0.f;
}
__device__ __forceinline__ float wredsum(float v){
    #pragma unroll
    for (int o = 16; o; o >>= 1) v += __shfl_xor_sync(0xffffffffu, v, o);
    return v;
}
__device__ __forceinline__ void bn_of(int slot, int k, float& mean, float& istd){
    float m = d_ssum[slot*Hd + k] * INV_NT;
    float v = d_ssq[slot*Hd + k] * INV_NT - m*m;
    if (v < 0.f) v = 0.f;
    mean = m;
    istd = rsqrtf(v + 1e-5f);
}
#define NEGINF __int_as_float(0xff800000)

// ---------------- init: zero stats + d_hp + bool dtype sniff ----------------
__global__ void k_init(const unsigned char* m){
    __shared__ int f0, fx;
    int tid = threadIdx.x;
    if (tid == 0){ f0 = 0; fx = 0; }
    for (int i = tid; i < 4*Hd; i += 256){ d_ssum[i] = 0.f; d_ssq[i] = 0.f; }
    for (int i = tid; i < Bb*Hd; i += 256) d_hp[i] = 0.f;
    __syncthreads();
    for (int i = tid; i < Bb*NJv; i += 256){
        if (m[i]){ if ((i & 3) == 0) atomicOr(&f0, 1); else atomicOr(&fx, 1); }
    }
    __syncthreads();
    if (tid == 0){
        int code;
        if (f0 && fx) code = 0;        // bytes everywhere -> uint8 bool
        else if (f0)  code = 1;        // only byte0 of each word -> int32
        else if (fx)  code = 2;        // only high bytes -> float32
        else          code = 0;
        d_boolcode = code;
    }
}

// ---------------- adj scan (float4) + pooled0 + t1 + stats slot0 ----------------
__global__ void __launch_bounds__(256) k_build(const float* __restrict__ adj,
                                               const float* __restrict__ x,
                                               const float* __restrict__ W1,
                                               const float* __restrict__ b1){
    __shared__ float s_sum[Hd], s_sq[Hd];
    for (int i = threadIdx.x; i < Hd; i += 256){ s_sum[i] = 0.f; s_sq[i] = 0.f; }
    __syncthreads();
    int warp = (blockIdx.x*256 + threadIdx.x) >> 5;
    int lane = threadIdx.x & 31;
    int b = warp / Nn;
    const float4* arow4 = (const float4*)(adj + (size_t)warp*Nn);   // 150 float4 per row
    const float2* x2 = (const float2*)x;
    float s0 = 0.f, s1 = 0.f;
    int cnt = 0;
    #pragma unroll
    for (int it = 0; it < 5; it++){
        int idx = it*32 + lane;
        bool valid = idx < 150;
        float4 v = valid ? arow4[idx] : make_float4(0.f,0.f,0.f,0.f);
        float vc[4] = {v.x, v.y, v.z, v.w};
        #pragma unroll
        for (int c = 0; c < 4; c++){
            unsigned bm = __ballot_sync(0xffffffffu, vc[c] != 0.f);
            if (vc[c] != 0.f){
                int m = idx*4 + c;
                int pos = cnt + __popc(bm & ((1u << lane) - 1u));
                if (pos < MAXNB) d_nbr[(size_t)warp*MAXNB + pos] = (unsigned short)m;
                float2 xv = x2[b*Nn + m];
                s0 += xv.x; s1 += xv.y;
            }
            cnt += __popc(bm);
        }
    }
    if (lane == 0) d_cnt[warp] = cnt > MAXNB ? MAXNB : cnt;
    #pragma unroll
    for (int o = 16; o; o >>= 1){
        s0 += __shfl_xor_sync(0xffffffffu, s0, o);
        s1 += __shfl_xor_sync(0xffffffffu, s1, o);
    }
    float* trow = d_t + (size_t)warp*Hd;
    #pragma unroll
    for (int i = 0; i < 4; i++){
        int d = lane + 32*i;
        float tv = fmaf(s0, W1[d], fmaf(s1, W1[Hd + d], b1[d]));
        trow[d] = tv;
        atomicAdd(&s_sum[d], tv);
        atomicAdd(&s_sq[d], tv*tv);
    }
    __syncthreads();
    for (int i = threadIdx.x; i < Hd; i += 256){
        atomicAdd(&d_ssum[i], s_sum[i]);
        atomicAdd(&d_ssq[i],  s_sq[i]);
    }
}

// ---------------- big GEMM: OUT = act(A) @ W + bias, stats(slotOut) ----------------
// 64-row tiles, 128 threads, 4 blocks/SM. Asel: 0->d_t 1->d_p ; Osel: 0->d_g 1->d_t
// mode 1 -> bn(slotIn)+relu on A-load
__global__ void __launch_bounds__(128, 4) k_gemm(const float* __restrict__ W,
                                                 const float* __restrict__ bias,
                                                 int Asel, int Osel, int mode,
                                                 int slotIn, int slotOut){
    extern __shared__ float sm[];
    float* Ws     = sm;                 // [32][LDW]  W chunk, k-major
    float* As     = sm + 32*LDW;        // [32][LDA]  A chunk, transposed [k][row], 64 rows
    float* s_sum  = As + 32*LDA;        // [128]
    float* s_sq   = s_sum + Hd;         // [128]
    float* s_mean = s_sq + Hd;          // [128]
    float* s_istd = s_mean + Hd;        // [128]
    const float* A   = Asel ? d_p : d_t;
    float*       OUT = Osel ? d_t : d_g;
    const int tid = threadIdx.x;
    const int rowBase = blockIdx.x * 64;

    for (int i = tid; i < Hd; i += 128){
        s_sum[i] = 0.f; s_sq[i] = 0.f;
        if (mode){
            float m, is; bn_of(slotIn, i, m, is);
            s_mean[i] = m; s_istd[i] = is;
        }
    }

    const int tx = tid & 15, ty = tid >> 4;       // ty 0..7
    const int r0 = ty*8;
    unsigned long long acc[4][8];
    #pragma unroll
    for (int p = 0; p < 4; p++)
        #pragma unroll
        for (int c = 0; c < 8; c++) acc[p][c] = 0ull;

    const int srow = tid >> 1;                    // 0..63
    const int kh   = (tid & 1) * 16;

    for (int kc = 0; kc < 4; kc++){
        __syncthreads();
        // stage W chunk [32][c]
        for (int i = tid; i < 32*32; i += 128){   // 1024 float4
            int k = i >> 5, c4 = i & 31;
            float4 w = ((const float4*)W)[(kc*32 + k)*32 + c4];
            *(float4*)(Ws + k*LDW + c4*4) = w;
        }
        // stage A chunk transposed with fused activation
        {
            const float* ar = A + (size_t)(rowBase + srow)*Hd + kc*32 + kh;
            #pragma unroll
            for (int j4 = 0; j4 < 4; j4++){
                float4 a = ((const float4*)ar)[j4];
                int kk = kh + j4*4;
                if (mode){
                    int kg = kc*32 + kk;
                    a.x = fmaxf((a.x - s_mean[kg+0])*s_istd[kg+0], 0.f);
                    a.y = fmaxf((a.y - s_mean[kg+1])*s_istd[kg+1], 0.f);
                    a.z = fmaxf((a.z - s_mean[kg+2])*s_istd[kg+2], 0.f);
                    a.w = fmaxf((a.w - s_mean[kg+3])*s_istd[kg+3], 0.f);
                }
                As[(kk+0)*LDA + srow] = a.x;
                As[(kk+1)*LDA + srow] = a.y;
                As[(kk+2)*LDA + srow] = a.z;
                As[(kk+3)*LDA + srow] = a.w;
            }
        }
        __syncthreads();
        #pragma unroll 2
        for (int kk = 0; kk < 32; kk++){
            const float* ak = As + kk*LDA + r0;
            unsigned long long a0 = *(const unsigned long long*)(ak + 0);
            unsigned long long a1 = *(const unsigned long long*)(ak + 2);
            unsigned long long a2 = *(const unsigned long long*)(ak + 4);
            unsigned long long a3 = *(const unsigned long long*)(ak + 6);
            const float* wk = Ws + kk*LDW + tx;
            #pragma unroll
            for (int c = 0; c < 8; c++){
                float wv = wk[16*c];
                unsigned long long wd = pk2(wv, wv);
                ffma2(acc[0][c], a0, wd);
                ffma2(acc[1][c], a1, wd);
                ffma2(acc[2][c], a2, wd);
                ffma2(acc[3][c], a3, wd);
            }
        }
    }
    // epilogue: bias, store, BN stats
    #pragma unroll
    for (int c = 0; c < 8; c++){
        int col = tx + 16*c;
        float bv = bias[col];
        float psum = 0.f, psq = 0.f;
        #pragma unroll
        for (int p = 0; p < 4; p++){
            float lo, hi; upk(acc[p][c], lo, hi);
            lo += bv; hi += bv;
            OUT[(size_t)(rowBase + r0 + 2*p)*Hd + col] = lo;
            OUT[(size_t)(rowBase + r0 + 2*p + 1)*Hd + col] = hi;
            psum += lo + hi;
            psq  += lo*lo + hi*hi;
        }
        atomicAdd(&s_sum[col], psum);
        atomicAdd(&s_sq[col],  psq);
    }
    __syncthreads();
    for (int i = tid; i < Hd; i += 128){
        atomicAdd(&d_ssum[slotOut*Hd + i], s_sum[i]);
        atomicAdd(&d_ssq[slotOut*Hd + i],  s_sq[i]);
    }
}

// ---------------- SpMM: pooled1 = sum over neighbors of relu(bn1(g)) ----------------
__global__ void __launch_bounds__(256) k_spmm(){
    int warp = (blockIdx.x*256 + threadIdx.x) >> 5;
    int lane = threadIdx.x & 31;
    int cnt = d_cnt[warp];
    int b = warp / Nn;
    const unsigned short* nb = d_nbr + (size_t)warp*MAXNB;
    float4 m4, i4;
    bn_of(1, lane*4 + 0, m4.x, i4.x);
    bn_of(1, lane*4 + 1, m4.y, i4.y);
    bn_of(1, lane*4 + 2, m4.z, i4.z);
    bn_of(1, lane*4 + 3, m4.w, i4.w);
    float s0 = 0.f, s1 = 0.f, s2 = 0.f, s3 = 0.f;
    const float4* gbase = (const float4*)(d_g + (size_t)b*Nn*Hd);
    int j = 0;
    for (; j + 4 <= cnt; j += 4){
        ushort4 nn = *(const ushort4*)(nb + j);
        float4 g0 = gbase[(size_t)nn.x*32 + lane];
        float4 g1 = gbase[(size_t)nn.y*32 + lane];
        float4 g2 = gbase[(size_t)nn.z*32 + lane];
        float4 g3 = gbase[(size_t)nn.w*32 + lane];
        s0 += fmaxf((g0.x - m4.x)*i4.x, 0.f) + fmaxf((g1.x - m4.x)*i4.x, 0.f)
            + fmaxf((g2.x - m4.x)*i4.x, 0.f) + fmaxf((g3.x - m4.x)*i4.x, 0.f);
        s1 += fmaxf((g0.y - m4.y)*i4.y, 0.f) + fmaxf((g1.y - m4.y)*i4.y, 0.f)
            + fmaxf((g2.y - m4.y)*i4.y, 0.f) + fmaxf((g3.y - m4.y)*i4.y, 0.f);
        s2 += fmaxf((g0.z - m4.z)*i4.z, 0.f) + fmaxf((g1.z - m4.z)*i4.z, 0.f)
            + fmaxf((g2.z - m4.z)*i4.z, 0.f) + fmaxf((g3.z - m4.z)*i4.z, 0.f);
        s3 += fmaxf((g0.w - m4.w)*i4.w, 0.f) + fmaxf((g1.w - m4.w)*i4.w, 0.f)
            + fmaxf((g2.w - m4.w)*i4.w, 0.f) + fmaxf((g3.w - m4.w)*i4.w, 0.f);
    }
    for (; j < cnt; j++){
        float4 g = gbase[(size_t)nb[j]*32 + lane];
        s0 += fmaxf((g.x - m4.x)*i4.x, 0.f);
        s1 += fmaxf((g.y - m4.y)*i4.y, 0.f);
        s2 += fmaxf((g.z - m4.z)*i4.z, 0.f);
        s3 += fmaxf((g.w - m4.w)*i4.w, 0.f);
    }
    ((float4*)(d_p + (size_t)warp*Hd))[lane] = make_float4(s0, s1, s2, s3);
}

// ---------------- graph pooling: partial sums, atomic into d_hp ----------------
__global__ void __launch_bounds__(128) k_hpool(const float* __restrict__ gp){
    int b = blockIdx.x;
    int sl = blockIdx.y;           // 0..7
    int d = threadIdx.x;
    float m, is; bn_of(3, d, m, is);
    float s = 0.f;
    int n0 = sl*75, n1 = n0 + 75;
    #pragma unroll 4
    for (int n = n0; n < n1; n++){
        float g = d_g[(size_t)(b*Nn + n)*Hd + d];
        s += gp[b*Nn + n] * fmaxf((g - m)*is, 0.f);
    }
    atomicAdd(&d_hp[b*Hd + d], s);
}

// ---------------- fused head: actor MLP + softmax + critic + gathers ----------------
// 256 threads: two groups of 128; group g handles candidates [g*15, g*15+15)
__global__ void __launch_bounds__(256) k_head(
    const int* __restrict__ candidate, const void* __restrict__ mask,
    const void* __restrict__ mask_mch, const float* __restrict__ dur,
    const int* __restrict__ a_index, const int* __restrict__ old_action,
    const float* __restrict__ mch_pool,
    const float* __restrict__ Wa1, const float* __restrict__ ba1,
    const float* __restrict__ Wa2, const float* __restrict__ ba2,
    const float* __restrict__ Wa3, const float* __restrict__ ba3,
    const float* __restrict__ Wc1, const float* __restrict__ bc1,
    const float* __restrict__ Wc2, const float* __restrict__ bc2,
    float* __restrict__ out)
{
    __shared__ float Abuf[NJv][Hd];
    __shared__ float Bbuf[NJv][Hd];
    __shared__ float hp_s[Hd], mp_s[Hd];
    __shared__ float scores[32];
    __shared__ float red[4];
    int b = blockIdx.x;
    int tid = threadIdx.x;
    int d = tid & 127;
    int grp = tid >> 7;
    int lane = tid & 31, wid = tid >> 5;
    int code = d_boolcode;
    float mn3, is3; bn_of(3, d, mn3, is3);

    if (grp == 0){
        float hv = d_hp[b*Hd + d];
        hp_s[d] = hv;
        out[O_HP + b*Hd + d] = hv;
        mp_s[d] = mch_pool[b*Hd + d];
    }
    for (int j = grp; j < NJv; j += 2){
        int node = candidate[b*NJv + j];
        float g = d_g[(size_t)(b*Nn + node)*Hd + d];
        Abuf[j][d] = fmaxf((g - mn3)*is3, 0.f);
    }
    __syncthreads();

    // actor layer 1 — shared (h_pooled, mch_pool) contribution once per thread
    float bs = ba1[d];
    for (int k = 0; k < Hd; k++){
        bs = fmaf(hp_s[k], Wa1[(Hd + k)*Hd + d], bs);
        bs = fmaf(mp_s[k], Wa1[(2*Hd + k)*Hd + d], bs);
    }
    const int j0 = grp * 15;
    {
        float accj[15];
        #pragma unroll
        for (int j = 0; j < 15; j++) accj[j] = bs;
        for (int k = 0; k < Hd; k += 4){
            float w0 = Wa1[(k+0)*Hd + d];
            float w1 = Wa1[(k+1)*Hd + d];
            float w2 = Wa1[(k+2)*Hd + d];
            float w3 = Wa1[(k+3)*Hd + d];
            #pragma unroll
            for (int j = 0; j < 15; j++){
                float4 a = *(const float4*)&Abuf[j0 + j][k];
                accj[j] = fmaf(a.x, w0, accj[j]);
                accj[j] = fmaf(a.y, w1, accj[j]);
                accj[j] = fmaf(a.z, w2, accj[j]);
                accj[j] = fmaf(a.w, w3, accj[j]);
            }
        }
        #pragma unroll
        for (int j = 0; j < 15; j++) Bbuf[j0 + j][d] = tanhf(accj[j]);
    }
    __syncthreads();
    // actor layer 2
    {
        float accj[15];
        float b2 = ba2[d];
        #pragma unroll
        for (int j = 0; j < 15; j++) accj[j] = b2;
        for (int k = 0; k < Hd; k += 4){
            float w0 = Wa2[(k+0)*Hd + d];
            float w1 = Wa2[(k+1)*Hd + d];
            float w2 = Wa2[(k+2)*Hd + d];
            float w3 = Wa2[(k+3)*Hd + d];
            #pragma unroll
            for (int j = 0; j < 15; j++){
                float4 a = *(const float4*)&Bbuf[j0 + j][k];
                accj[j] = fmaf(a.x, w0, accj[j]);
                accj[j] = fmaf(a.y, w1, accj[j]);
                accj[j] = fmaf(a.z, w2, accj[j]);
                accj[j] = fmaf(a.w, w3, accj[j]);
            }
        }
        #pragma unroll
        for (int j = 0; j < 15; j++) Abuf[j0 + j][d] = tanhf(accj[j]);
    }
    __syncthreads();
    // scores: 8 warps, warp-parallel dot with Wa3
    {
        float4 wv = ((const float4*)Wa3)[lane];
        for (int j = wid; j < NJv; j += 8){
            float4 av = ((const float4*)Abuf[j])[lane];
            float p = av.x*wv.x + av.y*wv.y + av.z*wv.z + av.w*wv.w;
            p = wredsum(p);
            if (lane == 0) scores[j] = (p + ba3[0]) * 10.f;
        }
    }
    // critic (group 0: 4 warps)
    if (grp == 0){
        float c = bc1[d];
        for (int k = 0; k < Hd; k++) c = fmaf(hp_s[k], Wc1[k*Hd + d], c);
        c = tanhf(c);
        float pv = wredsum(c * Wc2[d]);
        if (lane == 0) red[wid] = pv;
    }
    __syncthreads();
    if (tid == 0) out[O_V + b] = red[0] + red[1] + red[2] + red[3] + bc2[0];
    // softmax / entropy / log_a on warp 0
    if (wid == 0){
        float s = (lane < NJv) ? scores[lane] : NEGINF;
        if (lane < NJv && rdb(mask, (long long)b*NJv + lane, code)) s = NEGINF;
        float mx = s;
        #pragma unroll
        for (int o = 16; o; o >>= 1) mx = fmaxf(mx, __shfl_xor_sync(0xffffffffu, mx, o));
        float e = (s == NEGINF) ? 0.f : expf(s - mx);
        float se = wredsum(e);
        float lse = mx + logf(se);
        float logpi = s - lse;
        float pi = e / se;
        float ent = (pi > 0.f) ? (-pi * logpi) : 0.f;
        ent = wredsum(ent);
        if (lane == 0) out[O_ENT + b] = ent;
        int ai = a_index[b];
        if (lane == ai) out[O_LOGA + b] = logpi;
    }
    // gathers
    {
        int oa = old_action[b];
        if (grp == 0){
            float g = d_g[(size_t)(b*Nn + oa)*Hd + d];
            out[O_AF + b*Hd + d] = fmaxf((g - mn3)*is3, 0.f);
        }
        if (tid < NMv){
            out[O_AN + b*NMv + tid] = dur[(size_t)(b*Nn + oa)*NMv + tid];
            out[O_MMA + b*NMv + tid] = rdb(mask_mch, (long long)(b*Nn + oa)*NMv + tid, code) ? 1.f : 0.f;
        }
    }
}

// ---------------- launcher ----------------
extern "C" void kernel_launch(void* const* d_in, const int* in_sizes, int n_in,
                              void* d_out, int out_size) {
    const float* x         = (const float*)d_in[0];
    const float* graphpool = (const float*)d_in[1];
    // d_in[2] padded_nei unused
    const float* adj       = (const float*)d_in[3];
    const int*   candidate = (const int*)d_in[4];
    const void*  mask      = d_in[5];
    const void*  mask_mch  = d_in[6];
    const float* dur       = (const float*)d_in[7];
    const int*   a_index   = (const int*)d_in[8];
    const int*   old_act   = (const int*)d_in[9];
    const float* mch_pool  = (const float*)d_in[10];
    const float* W1_0 = (const float*)d_in[11]; const float* b1_0 = (const float*)d_in[12];
    const float* W2_0 = (const float*)d_in[13]; const float* b2_0 = (const float*)d_in[14];
    const float* W1_1 = (const float*)d_in[15]; const float* b1_1 = (const float*)d_in[16];
    const float* W2_1 = (const float*)d_in[17]; const float* b2_1 = (const float*)d_in[18];
    const float* Wa1  = (const float*)d_in[19]; const float* ba1  = (const float*)d_in[20];
    const float* Wa2  = (const float*)d_in[21]; const float* ba2  = (const float*)d_in[22];
    const float* Wa3  = (const float*)d_in[23]; const float* ba3  = (const float*)d_in[24];
    const float* Wc1  = (const float*)d_in[25]; const float* bc1  = (const float*)d_in[26];
    const float* Wc2  = (const float*)d_in[27]; const float* bc2  = (const float*)d_in[28];
    float* out = (float*)d_out;

    const int GEMM_SMEM = (32*LDW + 32*LDA + 4*Hd) * (int)sizeof(float);  // 27392
    cudaFuncSetAttribute(k_gemm, cudaFuncAttributeMaxDynamicSharedMemorySize, GEMM_SMEM);

    k_init<<<1, 256>>>((const unsigned char*)mask);                // zero stats/hp + bool sniff
    k_build<<<NT/8, 256>>>(adj, x, W1_0, b1_0);                    // t1 -> d_t, stats0
    k_gemm<<<NT/64, 128, GEMM_SMEM>>>(W2_0, b2_0, 0, 0, 1, 0, 1);  // t2 -> d_g, stats1
    k_spmm<<<NT/8, 256>>>();                                       // pooled1 -> d_p
    k_gemm<<<NT/64, 128, GEMM_SMEM>>>(W1_1, b1_1, 1, 1, 0, 0, 2);  // t3 -> d_t, stats2
    k_gemm<<<NT/64, 128, GEMM_SMEM>>>(W2_1, b2_1, 0, 0, 1, 2, 3);  // t4 -> d_g, stats3
    k_hpool<<<dim3(Bb, 8), 128>>>(graphpool);                      // partials -> d_hp
    k_head<<<Bb, 256>>>(candidate, mask, mask_mch, dur, a_index, old_act, mch_pool,
                        Wa1, ba1, Wa2, ba2, Wa3, ba3, Wc1, bc1, Wc2, bc2, out);
}